// round 15
// baseline (speedup 1.0000x reference)
#include <cuda_runtime.h>
#include <cuda_fp16.h>
#include <cstdint>
#include <math.h>

// ---------------- problem constants ----------------
#define TOK    4096   // B*T
#define BATCH  2
#define T_SEQ  2048
#define C_EMB  1024
#define NHEAD  16
#define HD     64
#define NHID   2816

// ---------------- scratch (static device globals) ----------------
__device__ float g_x2  [TOK * C_EMB];
__device__ __half g_abuf[TOK * 2 * NHID];        // large act split (silu out)
__device__ __half g_ab2 [TOK * 2 * C_EMB];       // small act split (rmsnorm / y)
__device__ __half g_bbuf[2 * NHID * C_EMB];      // weights plain fp16 (N-major)
__device__ __half g_qs [32 * T_SEQ * 128];       // q 2-term split
__device__ __half g_ks [32 * T_SEQ * 64];        // k plain fp16
__device__ __half g_vs [32 * T_SEQ * 64];        // v fp16
__device__ float2 g_rope[T_SEQ * 32];            // (cos, sin) per (t, pair)

// ---------------- small helpers ----------------
__device__ __forceinline__ uint32_t smem_to_u32(const void* p) {
    uint32_t a;
    asm("{ .reg .u64 t; cvta.to.shared.u64 t, %1; cvt.u32.u64 %0, t; }"
        : "=r"(a) : "l"(p));
    return a;
}
__device__ __forceinline__ void cpasync16(uint32_t dst, const void* src) {
    asm volatile("cp.async.cg.shared.global [%0], [%1], 16;"
                 :: "r"(dst), "l"(src) : "memory");
}
__device__ __forceinline__ void ldsm_x4(uint32_t* r, uint32_t addr) {
    asm volatile("ldmatrix.sync.aligned.m8n8.x4.shared.b16 {%0,%1,%2,%3}, [%4];"
                 : "=r"(r[0]), "=r"(r[1]), "=r"(r[2]), "=r"(r[3]) : "r"(addr));
}
__device__ __forceinline__ void ldsm_x4t(uint32_t* r, uint32_t addr) {
    asm volatile("ldmatrix.sync.aligned.m8n8.x4.trans.shared.b16 {%0,%1,%2,%3}, [%4];"
                 : "=r"(r[0]), "=r"(r[1]), "=r"(r[2]), "=r"(r[3]) : "r"(addr));
}
__device__ __forceinline__ void ldsm_x2(uint32_t* r, uint32_t addr) {
    asm volatile("ldmatrix.sync.aligned.m8n8.x2.shared.b16 {%0,%1}, [%2];"
                 : "=r"(r[0]), "=r"(r[1]) : "r"(addr));
}
__device__ __forceinline__ void mma_f16(float* d, const uint32_t* a, const uint32_t* b) {
    asm volatile("mma.sync.aligned.m16n8k16.row.col.f32.f16.f16.f32 "
                 "{%0,%1,%2,%3}, {%4,%5,%6,%7}, {%8,%9}, {%0,%1,%2,%3};"
                 : "+f"(d[0]), "+f"(d[1]), "+f"(d[2]), "+f"(d[3])
                 : "r"(a[0]), "r"(a[1]), "r"(a[2]), "r"(a[3]), "r"(b[0]), "r"(b[1]));
}
__device__ __forceinline__ uint32_t packh(float lo, float hi) {
    __half2 h = __floats2half2_rn(lo, hi);
    return *(uint32_t*)&h;
}

// ---------------- rope table ----------------
__global__ void rope_tab_k() {
    int t = blockIdx.x, i = threadIdx.x;          // 2048 x 32
    float theta = exp2f(-13.287712379549449f * ((float)i * (1.0f / 32.0f)));
    float s, c;
    sincosf((float)t * theta, &s, &c);
    g_rope[t * 32 + i] = make_float2(c, s);
}

// ==== fp16 warp-mma GEMM: D[M,N] = A'[M,KPA] @ B[N,KPA/2]^T (B wraps) =====
// EPI 1: C = R + A@B (fp32).  EPI 2: rope+split -> g_qs/g_ks/g_vs.
// EPI 3: silu(even)*odd -> hi|lo fp16 split into g_abuf.
#define GSTAGES     3
#define STAGE_BYTES 32768
#define GSMEM_TOTAL (GSTAGES * STAGE_BYTES)

template <int EPI>
__global__ __launch_bounds__(256)
void gemm_mma_k(const __half* __restrict__ A, const __half* __restrict__ B,
                const float* __restrict__ R, float* __restrict__ C, int KPA) {
    extern __shared__ char smem[];
    uint32_t sbase = smem_to_u32(smem);
    int tid = threadIdx.x, lane = tid & 31, wid = tid >> 5;
    int wm = wid & 1, wn = wid >> 1;
    int bx = blockIdx.x, by = blockIdx.y;
    int N = gridDim.x * 128;
    int NC = KPA >> 6;
    int NCB = NC >> 1;

    const char* Ag = (const char*)(A + (size_t)(by * 128) * KPA);
    const char* Bg = (const char*)(B + (size_t)(bx * 128) * (KPA >> 1));
    size_t lda = (size_t)KPA * 2;
    size_t ldb = (size_t)KPA;

    auto load_stage = [&](int stg, int c) {
        int cb = (c < NCB) ? c : (c - NCB);
        uint32_t sA = sbase + stg * STAGE_BYTES;
        uint32_t sB = sA + 16384;
        const char* Ac = Ag + (size_t)c * 128;
        const char* Bc = Bg + (size_t)cb * 128;
        #pragma unroll
        for (int i = 0; i < 4; i++) {
            int idx = i * 256 + tid;
            int r = idx >> 3, c16 = idx & 7;
            uint32_t dof = (uint32_t)(r * 128 + ((c16 ^ (r & 7)) << 4));
            cpasync16(sA + dof, Ac + (size_t)r * lda + c16 * 16);
            cpasync16(sB + dof, Bc + (size_t)r * ldb + c16 * 16);
        }
    };

    int aRow = lane & 15, aHi = lane >> 4;
    int bRow = lane & 7,  bHi = (lane >> 3) & 1;

    float acc[4][4][4];
    #pragma unroll
    for (int i = 0; i < 4; i++)
        #pragma unroll
        for (int j = 0; j < 4; j++)
            #pragma unroll
            for (int q = 0; q < 4; q++) acc[i][j][q] = 0.f;

    #pragma unroll
    for (int p = 0; p < GSTAGES; p++) {
        if (p < NC) load_stage(p, p);
        asm volatile("cp.async.commit_group;" ::: "memory");
    }

    for (int c = 0; c < NC; ++c) {
        int s = c % GSTAGES;
        asm volatile("cp.async.wait_group 2;" ::: "memory");
        __syncthreads();

        uint32_t sA = sbase + s * STAGE_BYTES;
        uint32_t sB = sA + 16384;
        #pragma unroll
        for (int ks = 0; ks < 4; ks++) {
            uint32_t af[4][4], bf[4][2];
            #pragma unroll
            for (int i = 0; i < 4; i++) {
                int m = wm * 64 + i * 16 + aRow;
                uint32_t addr = sA + m * 128 + (((ks * 2 + aHi) ^ (m & 7)) << 4);
                ldsm_x4(af[i], addr);
            }
            #pragma unroll
            for (int j = 0; j < 4; j++) {
                int n = wn * 32 + j * 8 + bRow;
                uint32_t addr = sB + n * 128 + (((ks * 2 + bHi) ^ (n & 7)) << 4);
                ldsm_x2(bf[j], addr);
            }
            #pragma unroll
            for (int i = 0; i < 4; i++)
                #pragma unroll
                for (int j = 0; j < 4; j++)
                    mma_f16(acc[i][j], af[i], bf[j]);
        }
        __syncthreads();
        int cn = c + GSTAGES;
        if (cn < NC) load_stage(s, cn);
        asm volatile("cp.async.commit_group;" ::: "memory");
    }

    int rowbase = by * 128 + wm * 64 + (lane >> 2);
    int colbase = bx * 128 + wn * 32 + (lane & 3) * 2;

    if (EPI == 1) {
        #pragma unroll
        for (int i = 0; i < 4; i++) {
            #pragma unroll
            for (int j = 0; j < 4; j++) {
                size_t r0 = (size_t)(rowbase + i * 16);
                int n0 = colbase + j * 8;
                float2 v0 = make_float2(acc[i][j][0], acc[i][j][1]);
                float2 v1 = make_float2(acc[i][j][2], acc[i][j][3]);
                float2 q0 = *(const float2*)(R + r0 * N + n0);
                float2 q1 = *(const float2*)(R + (r0 + 8) * N + n0);
                v0.x += q0.x; v0.y += q0.y; v1.x += q1.x; v1.y += q1.y;
                *(float2*)(C + r0 * N + n0)       = v0;
                *(float2*)(C + (r0 + 8) * N + n0) = v1;
            }
        }
    }
    if (EPI == 2) {   // rope + split: cols [0,1024) q, [1024,2048) k, rest v
        #pragma unroll
        for (int i = 0; i < 4; i++) {
            #pragma unroll
            for (int j = 0; j < 4; j++) {
                int n0 = colbase + j * 8;
                int sec = n0 >> 10;
                int cq = n0 & 1023;
                int hh = cq >> 6, ii = (cq & 63) >> 1;
                #pragma unroll
                for (int hf = 0; hf < 2; hf++) {
                    int row = rowbase + i * 16 + hf * 8;
                    float v0 = acc[i][j][hf * 2 + 0], v1 = acc[i][j][hf * 2 + 1];
                    int t = row & (T_SEQ - 1), b = row >> 11;
                    size_t base = (size_t)(b * NHEAD + hh) * T_SEQ + t;
                    if (sec == 0) {
                        float2 cs = g_rope[t * 32 + ii];
                        float e  = v0 * cs.x - v1 * cs.y;
                        float o2 = v0 * cs.y + v1 * cs.x;
                        float eh = __half2float(__float2half(e));
                        float oh = __half2float(__float2half(o2));
                        __half* qd = g_qs + base * 128;
                        *(uint32_t*)(qd + 2 * ii)      = packh(e, o2);
                        *(uint32_t*)(qd + 64 + 2 * ii) = packh(e - eh, o2 - oh);
                    } else if (sec == 1) {
                        float2 cs = g_rope[t * 32 + ii];
                        float e  = v0 * cs.x - v1 * cs.y;
                        float o2 = v0 * cs.y + v1 * cs.x;
                        *(uint32_t*)(g_ks + base * 64 + 2 * ii) = packh(e, o2);
                    } else {
                        *(uint32_t*)(g_vs + base * 64 + 2 * ii) = packh(v0, v1);
                    }
                }
            }
        }
    }
    if (EPI == 3) {   // silu(g1)*g2 -> 2-term split into g_abuf
        #pragma unroll
        for (int i = 0; i < 4; i++) {
            #pragma unroll
            for (int j = 0; j < 4; j++) {
                int jj = (colbase + j * 8) >> 1;
                #pragma unroll
                for (int hf = 0; hf < 2; hf++) {
                    int row = rowbase + i * 16 + hf * 8;
                    float g1 = acc[i][j][hf * 2 + 0], g2 = acc[i][j][hf * 2 + 1];
                    float v = (g1 / (1.f + __expf(-g1))) * g2;
                    float h = __half2float(__float2half(v));
                    __half* o = g_abuf + (size_t)row * (2 * NHID);
                    o[jj] = __float2half(v);
                    o[NHID + jj] = __float2half(v - h);
                }
            }
        }
    }
}

// ===== fp32 W [K][N] -> plain fp16 W^T [n*nStride + nOfs][K] ====
__global__ void split_wt_k(const float* __restrict__ W, __half* __restrict__ out,
                           int K, int N, int nOfs, int nStride) {
    __shared__ float tile[32][33];
    int k0 = blockIdx.y * 32, n0 = blockIdx.x * 32;
    int tx = threadIdx.x, ty = threadIdx.y;
    #pragma unroll
    for (int j = 0; j < 4; j++)
        tile[ty + 8 * j][tx] = W[(size_t)(k0 + ty + 8 * j) * N + n0 + tx];
    __syncthreads();
    #pragma unroll
    for (int j = 0; j < 4; j++) {
        int n = n0 + ty + 8 * j, k = k0 + tx;
        out[(size_t)(n * nStride + nOfs) * K + k] = __float2half(tile[tx][ty + 8 * j]);
    }
}

// ---- fused rmsnorm + 2-term split: x fp32 -> [M][2K] hi|lo fp16 ----------
__global__ void rmsnorm_split_k(const float* __restrict__ x,
                                const float* __restrict__ sc,
                                __half* __restrict__ out) {
    int row = blockIdx.x;
    int t = threadIdx.x;
    const float4* xr = (const float4*)(x + (size_t)row * C_EMB);
    const float4* s4 = (const float4*)sc;

    float4 v = xr[t];
    float ss = v.x*v.x + v.y*v.y + v.z*v.z + v.w*v.w;
    #pragma unroll
    for (int off = 16; off; off >>= 1) ss += __shfl_xor_sync(0xffffffffu, ss, off);

    __shared__ float part[8];
    __shared__ float inv_s;
    if ((t & 31) == 0) part[t >> 5] = ss;
    __syncthreads();
    if (t < 8) {
        float tot = part[t];
        #pragma unroll
        for (int off = 4; off; off >>= 1) tot += __shfl_xor_sync(0xffu, tot, off);
        if (t == 0) inv_s = rsqrtf(tot * (1.0f / C_EMB) + 1e-5f);
    }
    __syncthreads();
    float inv = inv_s;
    float4 w = s4[t];
    float a0 = v.x*inv*w.x, a1 = v.y*inv*w.y, a2 = v.z*inv*w.z, a3 = v.w*inv*w.w;

    float h0 = __half2float(__float2half(a0)), h1 = __half2float(__float2half(a1));
    float h2 = __half2float(__float2half(a2)), h3 = __half2float(__float2half(a3));
    uint2 hi = make_uint2(packh(a0, a1), packh(a2, a3));
    uint2 lo = make_uint2(packh(a0 - h0, a1 - h1), packh(a2 - h2, a3 - h3));
    char* o = (char*)(out + (size_t)row * (2 * C_EMB));
    *(uint2*)(o + t * 8)             = hi;
    *(uint2*)(o + C_EMB * 2 + t * 8) = lo;
}

// ================= tensor-core flash attention (fp16) ======================
#define A_QS   0
#define A_KS   17408
#define A_VS   35840
#define A_YM   54272
#define ASMEM  54528

__global__ __launch_bounds__(128)
void attn_mma_k(const __half* __restrict__ qs,
                const __half* __restrict__ ks,
                const __half* __restrict__ vs,
                const int* __restrict__ ymask,
                __half* __restrict__ yab) {
    extern __shared__ char smem[];
    uint32_t sb = smem_to_u32(smem);
    int tid = threadIdx.x, lane = tid & 31, wid = tid >> 5;
    int bx = (gridDim.x - 1) - blockIdx.x;
    int bh = blockIdx.y;
    int b = bh >> 4, head = bh & 15;
    int* ymsm = (int*)(smem + A_YM);

    const char* qg = (const char*)(qs + ((size_t)bh * T_SEQ + bx * 64) * 128);
    const char* kg = (const char*)(ks + (size_t)bh * T_SEQ * 64);
    const char* vg = (const char*)(vs + (size_t)bh * T_SEQ * 64);

    if (tid < 64) ymsm[tid] = ymask[b * 64 + tid];

    #pragma unroll
    for (int Lb = 0; Lb < 1024; Lb += 128) {
        int L = Lb + tid;
        int r = L >> 4, c = L & 15;
        cpasync16(sb + A_QS + r * 272 + c * 16, qg + (size_t)r * 256 + c * 16);
    }
    asm volatile("cp.async.commit_group;" ::: "memory");

    auto load_kv = [&](int stg, int kt) {
        uint32_t kd = sb + A_KS + stg * 9216;
        uint32_t vd = sb + A_VS + stg * 9216;
        const char* kc = kg + (size_t)(kt * 64) * 128;
        const char* vc = vg + (size_t)(kt * 64) * 128;
        #pragma unroll
        for (int Lb = 0; Lb < 512; Lb += 128) {
            int L = Lb + tid;
            int r = L >> 3, c = L & 7;
            cpasync16(kd + r * 144 + c * 16, kc + (size_t)r * 128 + c * 16);
            cpasync16(vd + r * 144 + c * 16, vc + (size_t)r * 128 + c * 16);
        }
    };

    load_kv(0, 0);
    asm volatile("cp.async.commit_group;" ::: "memory");

    asm volatile("cp.async.wait_group 1;" ::: "memory");
    __syncthreads();
    uint32_t qf[8][4];
    {
        int arow = wid * 16 + (lane & 15);
        int ahi  = lane >> 4;
        #pragma unroll
        for (int kk = 0; kk < 8; kk++) {
            uint32_t addr = sb + A_QS + arow * 272 + (kk * 16 + ahi * 8) * 2;
            ldsm_x4(qf[kk], addr);
        }
    }

    float o[8][4];
    #pragma unroll
    for (int j = 0; j < 8; j++)
        #pragma unroll
        for (int q = 0; q < 4; q++) o[j][q] = 0.f;
    float mA = -1e30f, mB = -1e30f, lA = 0.f, lB = 0.f;

    int rloc = wid * 16 + (lane >> 2);
    int gA = bx * 64 + rloc, gB = gA + 8;
    int ymA = 0, ymB = 0;
    __syncthreads();
    if (bx == 0) { ymA = ymsm[rloc]; ymB = ymsm[rloc + 8]; }

    int ntiles = bx + 1;
    int s = 0;
    for (int kt = 0; kt < ntiles; kt++) {
        if (kt + 1 < ntiles) {
            load_kv(s ^ 1, kt + 1);
            asm volatile("cp.async.commit_group;" ::: "memory");
            asm volatile("cp.async.wait_group 1;" ::: "memory");
        } else {
            asm volatile("cp.async.wait_group 0;" ::: "memory");
        }
        __syncthreads();

        uint32_t kds = sb + A_KS + s * 9216;
        uint32_t vds = sb + A_VS + s * 9216;

        float sf[8][4];
        #pragma unroll
        for (int j = 0; j < 8; j++)
            #pragma unroll
            for (int q = 0; q < 4; q++) sf[j][q] = 0.f;

        #pragma unroll
        for (int kk = 0; kk < 8; kk++) {
            int kc = kk & 3;
            uint32_t kb[8][2];
            #pragma unroll
            for (int jp = 0; jp < 4; jp++) {
                int n = jp * 16 + (lane & 7) + ((lane >> 4) & 1) * 8;
                uint32_t addr = kds + n * 144 + (kc * 16 + ((lane >> 3) & 1) * 8) * 2;
                uint32_t rr[4];
                ldsm_x4(rr, addr);
                kb[jp*2][0] = rr[0]; kb[jp*2][1] = rr[1];
                kb[jp*2+1][0] = rr[2]; kb[jp*2+1][1] = rr[3];
            }
            #pragma unroll
            for (int j = 0; j < 8; j++) mma_f16(sf[j], qf[kk], kb[j]);
        }

        bool diag = (kt == bx);
        int colb = (lane & 3) * 2;
        #pragma unroll
        for (int j = 0; j < 8; j++) {
            #pragma unroll
            for (int c = 0; c < 2; c++) {
                float vA = sf[j][c] * 0.125f;
                float vB = sf[j][c + 2] * 0.125f;
                if (diag) {
                    int gc = kt * 64 + j * 8 + colb + c;
                    int ymc = (bx == 0) ? ymsm[gc & 63] : 0;
                    if (!((gc <= gA) || (ymA && ymc))) vA = -1e30f;
                    if (!((gc <= gB) || (ymB && ymc))) vB = -1e30f;
                }
                sf[j][c] = vA; sf[j][c + 2] = vB;
            }
        }
        float nmA = mA, nmB = mB;
        #pragma unroll
        for (int j = 0; j < 8; j++) {
            nmA = fmaxf(nmA, fmaxf(sf[j][0], sf[j][1]));
            nmB = fmaxf(nmB, fmaxf(sf[j][2], sf[j][3]));
        }
        nmA = fmaxf(nmA, __shfl_xor_sync(0xffffffffu, nmA, 1));
        nmA = fmaxf(nmA, __shfl_xor_sync(0xffffffffu, nmA, 2));
        nmB = fmaxf(nmB, __shfl_xor_sync(0xffffffffu, nmB, 1));
        nmB = fmaxf(nmB, __shfl_xor_sync(0xffffffffu, nmB, 2));

        float corrA = __expf(mA - nmA), corrB = __expf(mB - nmB);
        mA = nmA; mB = nmB;
        float sumA = 0.f, sumB = 0.f;
        #pragma unroll
        for (int j = 0; j < 8; j++) {
            float p0 = __expf(sf[j][0] - nmA);
            float p1 = __expf(sf[j][1] - nmA);
            float p2 = __expf(sf[j][2] - nmB);
            float p3 = __expf(sf[j][3] - nmB);
            sumA += p0 + p1; sumB += p2 + p3;
            sf[j][0] = p0; sf[j][1] = p1; sf[j][2] = p2; sf[j][3] = p3;
        }
        sumA += __shfl_xor_sync(0xffffffffu, sumA, 1);
        sumA += __shfl_xor_sync(0xffffffffu, sumA, 2);
        sumB += __shfl_xor_sync(0xffffffffu, sumB, 1);
        sumB += __shfl_xor_sync(0xffffffffu, sumB, 2);
        lA = lA * corrA + sumA;
        lB = lB * corrB + sumB;
        #pragma unroll
        for (int j = 0; j < 8; j++) {
            o[j][0] *= corrA; o[j][1] *= corrA;
            o[j][2] *= corrB; o[j][3] *= corrB;
        }

        uint32_t pf[4][4];
        #pragma unroll
        for (int kk2 = 0; kk2 < 4; kk2++) {
            int j0 = 2 * kk2, j1 = j0 + 1;
            pf[kk2][0] = packh(sf[j0][0], sf[j0][1]);
            pf[kk2][1] = packh(sf[j0][2], sf[j0][3]);
            pf[kk2][2] = packh(sf[j1][0], sf[j1][1]);
            pf[kk2][3] = packh(sf[j1][2], sf[j1][3]);
        }

        #pragma unroll
        for (int kk2 = 0; kk2 < 4; kk2++) {
            #pragma unroll
            for (int jdp = 0; jdp < 4; jdp++) {
                int key = kk2 * 16 + ((lane >> 3) & 1) * 8 + (lane & 7);
                int dim = (jdp * 2 + (lane >> 4)) * 8;
                uint32_t rr[4];
                ldsm_x4t(rr, vds + key * 144 + dim * 2);
                mma_f16(o[jdp * 2],     pf[kk2], rr);
                mma_f16(o[jdp * 2 + 1], pf[kk2], rr + 2);
            }
        }

        __syncthreads();
        s ^= 1;
    }

    float iA = 1.f / lA, iB = 1.f / lB;
    int col0 = head * 64 + (lane & 3) * 2;
    size_t rowA = (size_t)(b * T_SEQ + gA);
    size_t rowB = rowA + 8;
    #pragma unroll
    for (int jd = 0; jd < 8; jd++) {
        float a0 = o[jd][0] * iA, a1 = o[jd][1] * iA;
        float b0 = o[jd][2] * iB, b1 = o[jd][3] * iB;
        float ha0 = __half2float(__float2half(a0)), ha1 = __half2float(__float2half(a1));
        float hb0 = __half2float(__float2half(b0)), hb1 = __half2float(__float2half(b1));
        uint32_t hiA = packh(a0, a1), hiB = packh(b0, b1);
        uint32_t loA = packh(a0 - ha0, a1 - ha1);
        uint32_t loB = packh(b0 - hb0, b1 - hb1);
        uint32_t* pA = (uint32_t*)(yab + rowA * (2 * C_EMB) + col0 + jd * 8);
        uint32_t* pB = (uint32_t*)(yab + rowB * (2 * C_EMB) + col0 + jd * 8);
        pA[0] = hiA; pA[C_EMB / 2] = loA;
        pB[0] = hiB; pB[C_EMB / 2] = loB;
    }
}

// ---------------- driver ----------------
extern "C" void kernel_launch(void* const* d_in, const int* in_sizes, int n_in,
                              void* d_out, int out_size) {
    const float* x      = (const float*)d_in[0];
    const int*   ymask  = (const int*)  d_in[1];
    const float* Wqkv   = (const float*)d_in[2];
    const float* Wattn  = (const float*)d_in[3];
    const float* scale1 = (const float*)d_in[4];
    const float* scale2 = (const float*)d_in[5];
    const float* Wfc1   = (const float*)d_in[6];
    const float* Wfc2   = (const float*)d_in[7];
    const float* Wmlp   = (const float*)d_in[8];
    float* out = (float*)d_out;

    float *x2;
    __half *ab, *ab2, *bb, *qsp, *ksp, *vsp;
    cudaGetSymbolAddress((void**)&x2,  g_x2);
    cudaGetSymbolAddress((void**)&ab,  g_abuf);
    cudaGetSymbolAddress((void**)&ab2, g_ab2);
    cudaGetSymbolAddress((void**)&bb,  g_bbuf);
    cudaGetSymbolAddress((void**)&qsp, g_qs);
    cudaGetSymbolAddress((void**)&ksp, g_ks);
    cudaGetSymbolAddress((void**)&vsp, g_vs);

    cudaFuncSetAttribute(gemm_mma_k<1>, cudaFuncAttributeMaxDynamicSharedMemorySize, GSMEM_TOTAL);
    cudaFuncSetAttribute(gemm_mma_k<2>, cudaFuncAttributeMaxDynamicSharedMemorySize, GSMEM_TOTAL);
    cudaFuncSetAttribute(gemm_mma_k<3>, cudaFuncAttributeMaxDynamicSharedMemorySize, GSMEM_TOTAL);
    cudaFuncSetAttribute(attn_mma_k,    cudaFuncAttributeMaxDynamicSharedMemorySize, ASMEM);

    dim3 wt8(32, 8);

    // ---- rope table + ab2 = split2(rmsnorm(x)) ----
    rope_tab_k<<<T_SEQ, 32>>>();
    rmsnorm_split_k<<<TOK, 256>>>(x, scale1, ab2);
    split_wt_k<<<dim3(3*C_EMB/32, C_EMB/32), wt8>>>(Wqkv, bb, C_EMB, 3*C_EMB, 0, 1);
    // qkv GEMM with fused rope+split epilogue -> qs/ks/vs
    gemm_mma_k<2><<<dim3(3*C_EMB/128, TOK/128), 256, GSMEM_TOTAL>>>(ab2, bb, nullptr, nullptr, 2*C_EMB);

    // ---- attention (writes y split into ab2) ----
    attn_mma_k<<<dim3(T_SEQ/64, BATCH*NHEAD), 128, ASMEM>>>(qsp, ksp, vsp, ymask, ab2);

    // ---- x2 = x + y @ Wattn ----
    split_wt_k<<<dim3(C_EMB/32, C_EMB/32), wt8>>>(Wattn, bb, C_EMB, C_EMB, 0, 1);
    gemm_mma_k<1><<<dim3(C_EMB/128, TOK/128), 256, GSMEM_TOTAL>>>(ab2, bb, x, x2, 2*C_EMB);

    // ---- ab2 = split2(rmsnorm(x2)); fused fc GEMM (interleaved) + silu -> ab ----
    rmsnorm_split_k<<<TOK, 256>>>(x2, scale2, ab2);
    split_wt_k<<<dim3(NHID/32, C_EMB/32), wt8>>>(Wfc1, bb, C_EMB, NHID, 0, 2);
    split_wt_k<<<dim3(NHID/32, C_EMB/32), wt8>>>(Wfc2, bb, C_EMB, NHID, 1, 2);
    gemm_mma_k<3><<<dim3(2*NHID/128, TOK/128), 256, GSMEM_TOTAL>>>(ab2, bb, nullptr, nullptr, 2*C_EMB);

    // ---- out = x2 + ab @ Wmlp ----
    split_wt_k<<<dim3(C_EMB/32, NHID/32), wt8>>>(Wmlp, bb, NHID, C_EMB, 0, 1);
    gemm_mma_k<1><<<dim3(C_EMB/128, TOK/128), 256, GSMEM_TOTAL>>>(ab, bb, x2, out, 2*NHID);
}